// round 1
// baseline (speedup 1.0000x reference)
#include <cuda_runtime.h>
#include <math.h>

#define N_NODES  50000
#define N_EDGES  800000
#define NODE_D   128
#define EDGE_D   100
#define EMB_D    92
#define N_GRAPHS 256
#define N_CONV   3
#define FC_D     128

// ---------------- scratch (device globals; no allocation allowed) ----------------
__device__ float g_x[N_NODES * NODE_D];        // node features
__device__ float g_AB[N_NODES * 512];          // [A(dst part incl bias) | B(src part)]
__device__ float g_agg[N_NODES * NODE_D];      // scatter-add target
__device__ float g_g16[N_EDGES * 16];          // 16-tap gaussian window per edge
__device__ int   g_k0[N_EDGES];                // window start per edge
__device__ float g_pool[N_GRAPHS * NODE_D];
__device__ float g_cnt[N_GRAPHS];

// ---------------- helpers ----------------
__device__ __forceinline__ float softplusf(float x) {
    return fmaxf(x, 0.f) + log1pf(__expf(-fabsf(x)));
}
__device__ __forceinline__ float sigmoidf(float x) {
    return 1.f / (1.f + __expf(-x));
}

// ---------------- zero kernels ----------------
__global__ void zero_agg_kernel() {
    int i = blockIdx.x * blockDim.x + threadIdx.x;
    if (i < N_NODES * NODE_D) g_agg[i] = 0.f;
}
__global__ void zero_pool_kernel() {
    int i = blockIdx.x * blockDim.x + threadIdx.x;
    if (i < N_GRAPHS * NODE_D) g_pool[i] = 0.f;
    if (i < N_GRAPHS) g_cnt[i] = 0.f;
}

// ---------------- x0 = embedding[z] @ emb_w + emb_b ----------------
__global__ void embed_kernel(const int* __restrict__ z,
                             const float* __restrict__ emb,
                             const float* __restrict__ W,
                             const float* __restrict__ b) {
    __shared__ float er[EMB_D];
    int n = blockIdx.x;
    int zi = z[n];
    if (threadIdx.x < EMB_D) er[threadIdx.x] = emb[zi * EMB_D + threadIdx.x];
    __syncthreads();
    int c = threadIdx.x;
    float acc = b[c];
#pragma unroll 4
    for (int k = 0; k < EMB_D; k++) acc += er[k] * W[k * NODE_D + c];
    g_x[(size_t)n * NODE_D + c] = acc;
}

// ---------------- per-edge geometry: distance + 16-tap gaussian window ----------------
__global__ void edge_geom_kernel(const float* __restrict__ R,
                                 const int* __restrict__ src,
                                 const int* __restrict__ dst) {
    int e = blockIdx.x * blockDim.x + threadIdx.x;
    if (e >= N_EDGES) return;
    int s = src[e], d = dst[e];
    float dx = R[s * 3 + 0] - R[d * 3 + 0];
    float dy = R[s * 3 + 1] - R[d * 3 + 1];
    float dz = R[s * 3 + 2] - R[d * 3 + 2];
    float dist = sqrtf(dx * dx + dy * dy + dz * dz);
    const float delta = 6.0f / 99.0f;
    const float coeff = -0.5f / (delta * delta);
    int kc = __float2int_rn(dist / delta);
    int k0 = min(max(kc - 7, 0), EDGE_D - 16);
    g_k0[e] = k0;
    float vals[16];
#pragma unroll
    for (int t = 0; t < 16; t++) {
        float u = dist - (float)(k0 + t) * delta;
        vals[t] = expf(coeff * u * u);
    }
    float4* out = (float4*)(g_g16 + (size_t)e * 16);
#pragma unroll
    for (int q = 0; q < 4; q++)
        out[q] = make_float4(vals[4 * q], vals[4 * q + 1], vals[4 * q + 2], vals[4 * q + 3]);
}

// ---------------- AB = x @ [W1 | W2] (+bias on first 256 cols) ----------------
// Wl: conv_w + l*356*256.  cols 0..255 use rows 0..127 (dst part, +conv_b),
//                          cols 256..511 use rows 128..255 (src part).
#define GM 64
#define GN 64
#define GK 16
__global__ void gemm_ab_kernel(const float* __restrict__ Wl,
                               const float* __restrict__ bias) {
    __shared__ float As[GK][GM];
    __shared__ float Bs[GK][GN];
    int tid = threadIdx.x;           // 256 threads
    int bn = blockIdx.x;             // 0..7 column tiles
    int bm = blockIdx.y;             // row tiles
    int colbase = bn * GN;
    int half = (colbase >= 256) ? 1 : 0;
    const float* W = Wl + (half ? 128 * 256 : 0);
    int wcol = colbase & 255;
    int row0 = bm * GM;

    int lr = tid >> 2;               // A loader: row in tile (0..63)
    int lk = (tid & 3) * 4;          // A loader: k offset
    int br = tid >> 4;               // B loader: k (0..15)
    int bc = (tid & 15) * 4;         // B loader: col offset

    int ty = tid >> 4, tx = tid & 15;
    float acc[4][4] = {};

    for (int k0 = 0; k0 < NODE_D; k0 += GK) {
        int arow = row0 + lr;
        float4 av = make_float4(0.f, 0.f, 0.f, 0.f);
        if (arow < N_NODES) av = *(const float4*)(g_x + (size_t)arow * NODE_D + k0 + lk);
        As[lk + 0][lr] = av.x; As[lk + 1][lr] = av.y;
        As[lk + 2][lr] = av.z; As[lk + 3][lr] = av.w;
        float4 bv = *(const float4*)(W + (size_t)(k0 + br) * 256 + wcol + bc);
        *(float4*)&Bs[br][bc] = bv;
        __syncthreads();
#pragma unroll
        for (int k = 0; k < GK; k++) {
            float4 a = *(float4*)&As[k][ty * 4];
            float4 b = *(float4*)&Bs[k][tx * 4];
            acc[0][0] += a.x * b.x; acc[0][1] += a.x * b.y; acc[0][2] += a.x * b.z; acc[0][3] += a.x * b.w;
            acc[1][0] += a.y * b.x; acc[1][1] += a.y * b.y; acc[1][2] += a.y * b.z; acc[1][3] += a.y * b.w;
            acc[2][0] += a.z * b.x; acc[2][1] += a.z * b.y; acc[2][2] += a.z * b.z; acc[2][3] += a.z * b.w;
            acc[3][0] += a.w * b.x; acc[3][1] += a.w * b.y; acc[3][2] += a.w * b.z; acc[3][3] += a.w * b.w;
        }
        __syncthreads();
    }
    int cg = colbase + tx * 4;
    float4 bv = make_float4(0.f, 0.f, 0.f, 0.f);
    if (!half) bv = *(const float4*)(bias + cg);
#pragma unroll
    for (int i = 0; i < 4; i++) {
        int r = row0 + ty * 4 + i;
        if (r < N_NODES) {
            float4 o = make_float4(acc[i][0] + bv.x, acc[i][1] + bv.y,
                                   acc[i][2] + bv.z, acc[i][3] + bv.w);
            *(float4*)(g_AB + (size_t)r * 512 + cg) = o;
        }
    }
}

// ---------------- edge conv: z = A[dst] + B[src] + sum_k g_k W3[k]; msg; scatter ----------------
// one warp per edge; W3 (100x256) staged in dynamic smem
__global__ void edge_conv_kernel(const int* __restrict__ src,
                                 const int* __restrict__ dst,
                                 const float* __restrict__ Wl) {
    extern __shared__ float W3s[];   // 100*256 floats = 100 KB
    const float* W3g = Wl + 256 * 256;
    for (int i = threadIdx.x; i < EDGE_D * 256; i += blockDim.x)
        W3s[i] = W3g[i];
    __syncthreads();

    int warpId = threadIdx.x >> 5;
    int lane = threadIdx.x & 31;
    int warpsPerGrid = (blockDim.x >> 5) * gridDim.x;

    for (int e = blockIdx.x * (blockDim.x >> 5) + warpId; e < N_EDGES; e += warpsPerGrid) {
        int s = 0, dn = 0, k0 = 0;
        if (lane == 0) { s = src[e]; dn = dst[e]; k0 = g_k0[e]; }
        s  = __shfl_sync(0xffffffffu, s, 0);
        dn = __shfl_sync(0xffffffffu, dn, 0);
        k0 = __shfl_sync(0xffffffffu, k0, 0);
        float gv = (lane < 16) ? g_g16[(size_t)e * 16 + lane] : 0.f;

        const float4* Ad = (const float4*)(g_AB + (size_t)dn * 512);
        const float4* Bs_ = (const float4*)(g_AB + (size_t)s * 512 + 256);
        float4 z1 = Ad[lane];       // cols 4l..4l+3      (first half)
        float4 z2 = Ad[32 + lane];  // cols 128+4l..      (second half)
        float4 t1 = Bs_[lane];
        float4 t2 = Bs_[32 + lane];
        z1.x += t1.x; z1.y += t1.y; z1.z += t1.z; z1.w += t1.w;
        z2.x += t2.x; z2.y += t2.y; z2.z += t2.z; z2.w += t2.w;

#pragma unroll
        for (int k = 0; k < 16; k++) {
            float gk = __shfl_sync(0xffffffffu, gv, k);
            const float* wr = W3s + (size_t)(k0 + k) * 256;
            float4 w1 = *(const float4*)(wr + 4 * lane);
            float4 w2 = *(const float4*)(wr + 128 + 4 * lane);
            z1.x += gk * w1.x; z1.y += gk * w1.y; z1.z += gk * w1.z; z1.w += gk * w1.w;
            z2.x += gk * w2.x; z2.y += gk * w2.y; z2.z += gk * w2.z; z2.w += gk * w2.w;
        }

        float4 m;
        m.x = sigmoidf(z1.x) * softplusf(z2.x);
        m.y = sigmoidf(z1.y) * softplusf(z2.y);
        m.z = sigmoidf(z1.z) * softplusf(z2.z);
        m.w = sigmoidf(z1.w) * softplusf(z2.w);

        float* base = g_agg + (size_t)dn * NODE_D + 4 * lane;
        atomicAdd(base + 0, m.x);
        atomicAdd(base + 1, m.y);
        atomicAdd(base + 2, m.z);
        atomicAdd(base + 3, m.w);
    }
}

// ---------------- node update: x = softplus(LN(agg)*g+b + x) ----------------
__global__ void node_update_kernel(const float* __restrict__ lng,
                                   const float* __restrict__ lnb) {
    int n = blockIdx.x * 8 + (threadIdx.x >> 5);
    if (n >= N_NODES) return;
    int lane = threadIdx.x & 31;
    float4 a = ((const float4*)g_agg)[(size_t)n * 32 + lane];
    float s = a.x + a.y + a.z + a.w;
    float ss = a.x * a.x + a.y * a.y + a.z * a.z + a.w * a.w;
#pragma unroll
    for (int off = 16; off > 0; off >>= 1) {
        s  += __shfl_xor_sync(0xffffffffu, s, off);
        ss += __shfl_xor_sync(0xffffffffu, ss, off);
    }
    float mu = s * (1.f / 128.f);
    float var = ss * (1.f / 128.f) - mu * mu;
    float rinv = rsqrtf(var + 1e-5f);
    float4 gg = ((const float4*)lng)[lane];
    float4 bb = ((const float4*)lnb)[lane];
    float4 xo = ((float4*)g_x)[(size_t)n * 32 + lane];
    float4 o;
    o.x = softplusf((a.x - mu) * rinv * gg.x + bb.x + xo.x);
    o.y = softplusf((a.y - mu) * rinv * gg.y + bb.y + xo.y);
    o.z = softplusf((a.z - mu) * rinv * gg.z + bb.z + xo.z);
    o.w = softplusf((a.w - mu) * rinv * gg.w + bb.w + xo.w);
    ((float4*)g_x)[(size_t)n * 32 + lane] = o;
}

// ---------------- mean pool (atomic) ----------------
__global__ void pool_kernel(const int* __restrict__ batch) {
    int n = blockIdx.x * 8 + (threadIdx.x >> 5);
    if (n >= N_NODES) return;
    int lane = threadIdx.x & 31;
    int b = 0;
    if (lane == 0) b = batch[n];
    b = __shfl_sync(0xffffffffu, b, 0);
    float4 v = ((const float4*)g_x)[(size_t)n * 32 + lane];
    float* base = g_pool + (size_t)b * NODE_D + 4 * lane;
    atomicAdd(base + 0, v.x);
    atomicAdd(base + 1, v.y);
    atomicAdd(base + 2, v.z);
    atomicAdd(base + 3, v.w);
    if (lane == 0) atomicAdd(g_cnt + b, 1.f);
}

// ---------------- head MLP: one block per graph ----------------
__global__ void head_kernel(const float* __restrict__ cfc_w, const float* __restrict__ cfc_b,
                            const float* __restrict__ fc_w,  const float* __restrict__ fc_b,
                            const float* __restrict__ out_w, const float* __restrict__ out_b,
                            float* __restrict__ out) {
    __shared__ float h0[FC_D], h1[FC_D];
    __shared__ float red[4];
    int g = blockIdx.x, c = threadIdx.x;
    float cn = fmaxf(g_cnt[g], 1.f);
    h0[c] = g_pool[(size_t)g * NODE_D + c] / cn;
    __syncthreads();
    float acc = cfc_b[c];
#pragma unroll 4
    for (int k = 0; k < NODE_D; k++) acc += h0[k] * cfc_w[k * FC_D + c];
    h1[c] = softplusf(acc);
    __syncthreads();
    acc = fc_b[c];
#pragma unroll 4
    for (int k = 0; k < FC_D; k++) acc += h1[k] * fc_w[k * FC_D + c];
    h0[c] = softplusf(acc);
    __syncthreads();
    acc = fc_b[FC_D + c];
#pragma unroll 4
    for (int k = 0; k < FC_D; k++) acc += h0[k] * fc_w[FC_D * FC_D + k * FC_D + c];
    h1[c] = softplusf(acc);
    __syncthreads();
    float p = h1[c] * out_w[c];
#pragma unroll
    for (int off = 16; off > 0; off >>= 1) p += __shfl_xor_sync(0xffffffffu, p, off);
    if ((c & 31) == 0) red[c >> 5] = p;
    __syncthreads();
    if (c == 0) out[g] = red[0] + red[1] + red[2] + red[3] + out_b[0];
}

// ---------------- launch ----------------
extern "C" void kernel_launch(void* const* d_in, const int* in_sizes, int n_in,
                              void* d_out, int out_size) {
    const int*   z         = (const int*)d_in[0];
    const float* R         = (const float*)d_in[1];
    const int*   ei        = (const int*)d_in[2];     // [2, E]: row0=src, row1=dst
    const int*   batch     = (const int*)d_in[3];
    const float* embedding = (const float*)d_in[4];
    const float* emb_w     = (const float*)d_in[5];
    const float* emb_b     = (const float*)d_in[6];
    const float* conv_w    = (const float*)d_in[7];   // [3, 356, 256]
    const float* conv_b    = (const float*)d_in[8];   // [3, 256]
    const float* ln_g      = (const float*)d_in[9];   // [3, 128]
    const float* ln_b      = (const float*)d_in[10];
    const float* cfc_w     = (const float*)d_in[11];
    const float* cfc_b     = (const float*)d_in[12];
    const float* fc_w      = (const float*)d_in[13];
    const float* fc_b      = (const float*)d_in[14];
    const float* out_w     = (const float*)d_in[15];
    const float* out_b     = (const float*)d_in[16];
    float* out = (float*)d_out;

    const int* src = ei;
    const int* dst = ei + N_EDGES;

    static bool attr_set = false;
    if (!attr_set) {
        cudaFuncSetAttribute(edge_conv_kernel,
                             cudaFuncAttributeMaxDynamicSharedMemorySize,
                             EDGE_D * 256 * sizeof(float));
        attr_set = true;
    }

    // pool buffers zero
    zero_pool_kernel<<<(N_GRAPHS * NODE_D + 255) / 256, 256>>>();
    // initial embedding
    embed_kernel<<<N_NODES, NODE_D>>>(z, embedding, emb_w, emb_b);
    // per-edge geometry (reused by all 3 layers)
    edge_geom_kernel<<<(N_EDGES + 255) / 256, 256>>>(R, src, dst);

    for (int l = 0; l < N_CONV; l++) {
        const float* Wl = conv_w + (size_t)l * 356 * 256;
        const float* bl = conv_b + (size_t)l * 256;
        dim3 ggrid(512 / GN, (N_NODES + GM - 1) / GM);
        gemm_ab_kernel<<<ggrid, 256>>>(Wl, bl);
        zero_agg_kernel<<<(N_NODES * NODE_D + 255) / 256, 256>>>();
        edge_conv_kernel<<<296, 256, EDGE_D * 256 * sizeof(float)>>>(src, dst, Wl);
        node_update_kernel<<<(N_NODES + 7) / 8, 256>>>(ln_g + l * NODE_D, ln_b + l * NODE_D);
    }

    pool_kernel<<<(N_NODES + 7) / 8, 256>>>(batch);
    head_kernel<<<N_GRAPHS, FC_D>>>(cfc_w, cfc_b, fc_w, fc_b, out_w, out_b, out);
}

// round 2
// speedup vs baseline: 1.8925x; 1.8925x over previous
#include <cuda_runtime.h>
#include <math.h>

#define N_NODES  50000
#define N_EDGES  800000
#define NODE_D   128
#define EDGE_D   100
#define EMB_D    92
#define N_GRAPHS 256
#define N_CONV   3
#define FC_D     128

#define DELTA    (6.0f / 99.0f)
#define N_T      1800
#define H_T      (DELTA / 16.0f)

// ---------------- scratch (device globals) ----------------
__device__ float g_x[N_NODES * NODE_D];
__device__ float g_AB[N_NODES * 512];
__device__ float g_tab[N_T * 256];
__device__ int   g_deg[N_NODES];
__device__ int   g_off[N_NODES];
__device__ int   g_rowstart[N_NODES + 1];
__device__ int   g_srcs[N_EDGES];
__device__ int   g_tidx[N_EDGES];
__device__ float g_frac[N_EDGES];
__device__ float g_pool[N_GRAPHS * NODE_D];
__device__ float g_cnt[N_GRAPHS];

// ---------------- helpers ----------------
__device__ __forceinline__ float softplusf(float x) {
    return fmaxf(x, 0.f) + log1pf(__expf(-fabsf(x)));
}
__device__ __forceinline__ float sigmoidf(float x) {
    return 1.f / (1.f + __expf(-x));
}

// ---------------- zero kernels ----------------
__global__ void zero_misc_kernel() {
    int i = blockIdx.x * blockDim.x + threadIdx.x;
    if (i < N_NODES) g_deg[i] = 0;
    if (i < N_GRAPHS * NODE_D) g_pool[i] = 0.f;
    if (i < N_GRAPHS) g_cnt[i] = 0.f;
}

// ---------------- x0 = embedding[z] @ emb_w + emb_b ----------------
__global__ void embed_kernel(const int* __restrict__ z,
                             const float* __restrict__ emb,
                             const float* __restrict__ W,
                             const float* __restrict__ b) {
    __shared__ float er[EMB_D];
    int n = blockIdx.x;
    int zi = z[n];
    if (threadIdx.x < EMB_D) er[threadIdx.x] = emb[zi * EMB_D + threadIdx.x];
    __syncthreads();
    int c = threadIdx.x;
    float acc = b[c];
#pragma unroll 4
    for (int k = 0; k < EMB_D; k++) acc += er[k] * W[k * NODE_D + c];
    g_x[(size_t)n * NODE_D + c] = acc;
}

// ---------------- counting sort by dst ----------------
__global__ void hist_kernel(const int* __restrict__ dst) {
    int e = blockIdx.x * blockDim.x + threadIdx.x;
    if (e < N_EDGES) atomicAdd(&g_deg[dst[e]], 1);
}

__global__ void scan_kernel() {   // single block, 1024 threads
    __shared__ int partial[1024];
    const int T = 1024, CH = (N_NODES + T - 1) / T;
    int t = threadIdx.x;
    int base = t * CH;
    int s = 0;
    for (int i = 0; i < CH; i++) {
        int idx = base + i;
        if (idx < N_NODES) s += g_deg[idx];
    }
    partial[t] = s;
    __syncthreads();
    for (int off = 1; off < T; off <<= 1) {
        int v = (t >= off) ? partial[t - off] : 0;
        __syncthreads();
        partial[t] += v;
        __syncthreads();
    }
    int run = (t > 0) ? partial[t - 1] : 0;  // exclusive prefix
    for (int i = 0; i < CH; i++) {
        int idx = base + i;
        if (idx < N_NODES) {
            g_rowstart[idx] = run;
            g_off[idx] = run;
            run += g_deg[idx];
        }
    }
    if (t == T - 1) g_rowstart[N_NODES] = run;
}

// scatter into sorted order; also compute distance -> (tidx, frac)
__global__ void scatter_kernel(const float* __restrict__ R,
                               const int* __restrict__ src,
                               const int* __restrict__ dst) {
    int e = blockIdx.x * blockDim.x + threadIdx.x;
    if (e >= N_EDGES) return;
    int s = src[e], d = dst[e];
    float dx = R[s * 3 + 0] - R[d * 3 + 0];
    float dy = R[s * 3 + 1] - R[d * 3 + 1];
    float dz = R[s * 3 + 2] - R[d * 3 + 2];
    float dist = sqrtf(dx * dx + dy * dy + dz * dz);
    float u = fminf(dist / H_T, (float)(N_T - 2));
    int   t = (int)u;
    float f = u - (float)t;
    int pos = atomicAdd(&g_off[d], 1);
    g_srcs[pos] = s;
    g_tidx[pos] = t;
    g_frac[pos] = f;
}

// ---------------- per-layer table: T[t] = gaussians(t*h) @ W3 ----------------
__global__ void build_tab_kernel(const float* __restrict__ Wl) {
    __shared__ float gs[EDGE_D];
    const float* W3 = Wl + 256 * 256;
    int t = blockIdx.x;
    float d = (float)t * H_T;
    const float coeff = -0.5f / (DELTA * DELTA);
    if (threadIdx.x < EDGE_D) {
        float u = d - (float)threadIdx.x * DELTA;
        gs[threadIdx.x] = expf(coeff * u * u);
    }
    __syncthreads();
    int c = threadIdx.x;
    float acc = 0.f;
#pragma unroll 4
    for (int k = 0; k < EDGE_D; k++) acc += gs[k] * W3[k * 256 + c];
    g_tab[(size_t)t * 256 + c] = acc;
}

// ---------------- AB = x @ [W1 | W2] (+bias on first 256 cols) ----------------
#define GM 64
#define GN 64
#define GK 16
__global__ void gemm_ab_kernel(const float* __restrict__ Wl,
                               const float* __restrict__ bias) {
    __shared__ float As[GK][GM];
    __shared__ float Bs[GK][GN];
    int tid = threadIdx.x;
    int bn = blockIdx.x;
    int bm = blockIdx.y;
    int colbase = bn * GN;
    int half = (colbase >= 256) ? 1 : 0;
    const float* W = Wl + (half ? 128 * 256 : 0);
    int wcol = colbase & 255;
    int row0 = bm * GM;

    int lr = tid >> 2;
    int lk = (tid & 3) * 4;
    int br = tid >> 4;
    int bc = (tid & 15) * 4;

    int ty = tid >> 4, tx = tid & 15;
    float acc[4][4] = {};

    for (int k0 = 0; k0 < NODE_D; k0 += GK) {
        int arow = row0 + lr;
        float4 av = make_float4(0.f, 0.f, 0.f, 0.f);
        if (arow < N_NODES) av = *(const float4*)(g_x + (size_t)arow * NODE_D + k0 + lk);
        As[lk + 0][lr] = av.x; As[lk + 1][lr] = av.y;
        As[lk + 2][lr] = av.z; As[lk + 3][lr] = av.w;
        float4 bv = *(const float4*)(W + (size_t)(k0 + br) * 256 + wcol + bc);
        *(float4*)&Bs[br][bc] = bv;
        __syncthreads();
#pragma unroll
        for (int k = 0; k < GK; k++) {
            float4 a = *(float4*)&As[k][ty * 4];
            float4 b = *(float4*)&Bs[k][tx * 4];
            acc[0][0] += a.x * b.x; acc[0][1] += a.x * b.y; acc[0][2] += a.x * b.z; acc[0][3] += a.x * b.w;
            acc[1][0] += a.y * b.x; acc[1][1] += a.y * b.y; acc[1][2] += a.y * b.z; acc[1][3] += a.y * b.w;
            acc[2][0] += a.z * b.x; acc[2][1] += a.z * b.y; acc[2][2] += a.z * b.z; acc[2][3] += a.z * b.w;
            acc[3][0] += a.w * b.x; acc[3][1] += a.w * b.y; acc[3][2] += a.w * b.z; acc[3][3] += a.w * b.w;
        }
        __syncthreads();
    }
    int cg = colbase + tx * 4;
    float4 bv = make_float4(0.f, 0.f, 0.f, 0.f);
    if (!half) bv = *(const float4*)(bias + cg);
#pragma unroll
    for (int i = 0; i < 4; i++) {
        int r = row0 + ty * 4 + i;
        if (r < N_NODES) {
            float4 o = make_float4(acc[i][0] + bv.x, acc[i][1] + bv.y,
                                   acc[i][2] + bv.z, acc[i][3] + bv.w);
            *(float4*)(g_AB + (size_t)r * 512 + cg) = o;
        }
    }
}

// ---------------- fused edge aggregation + LN + residual + softplus ----------------
// one warp per dst node; edges sorted by dst → register accumulation, no atomics
__global__ void edge_agg_kernel(const float* __restrict__ lng,
                                const float* __restrict__ lnb) {
    int n = blockIdx.x * 8 + (threadIdx.x >> 5);
    if (n >= N_NODES) return;
    int lane = threadIdx.x & 31;

    int row = g_rowstart[n];
    int end = g_rowstart[n + 1];

    const float4* Arow = (const float4*)(g_AB + (size_t)n * 512);
    float4 a1 = Arow[lane];        // cols 4l..4l+3    (z1 part, incl bias)
    float4 a2 = Arow[32 + lane];   // cols 128+4l..    (z2 part)

    float4 acc = make_float4(0.f, 0.f, 0.f, 0.f);

    for (int e = row; e < end; e++) {
        int   s = __ldg(&g_srcs[e]);
        int   t = __ldg(&g_tidx[e]);
        float f = __ldg(&g_frac[e]);

        const float4* Brow = (const float4*)(g_AB + (size_t)s * 512 + 256);
        float4 b1 = Brow[lane];
        float4 b2 = Brow[32 + lane];
        const float4* Tlo = (const float4*)(g_tab + (size_t)t * 256);
        const float4* Thi = (const float4*)(g_tab + (size_t)(t + 1) * 256);
        float4 w1l = Tlo[lane],      w1h = Thi[lane];
        float4 w2l = Tlo[32 + lane], w2h = Thi[32 + lane];

        float4 z1, z2;
        z1.x = a1.x + b1.x + w1l.x + f * (w1h.x - w1l.x);
        z1.y = a1.y + b1.y + w1l.y + f * (w1h.y - w1l.y);
        z1.z = a1.z + b1.z + w1l.z + f * (w1h.z - w1l.z);
        z1.w = a1.w + b1.w + w1l.w + f * (w1h.w - w1l.w);
        z2.x = a2.x + b2.x + w2l.x + f * (w2h.x - w2l.x);
        z2.y = a2.y + b2.y + w2l.y + f * (w2h.y - w2l.y);
        z2.z = a2.z + b2.z + w2l.z + f * (w2h.z - w2l.z);
        z2.w = a2.w + b2.w + w2l.w + f * (w2h.w - w2l.w);

        acc.x += sigmoidf(z1.x) * softplusf(z2.x);
        acc.y += sigmoidf(z1.y) * softplusf(z2.y);
        acc.z += sigmoidf(z1.z) * softplusf(z2.z);
        acc.w += sigmoidf(z1.w) * softplusf(z2.w);
    }

    // LayerNorm over 128 channels (warp reduction)
    float s  = acc.x + acc.y + acc.z + acc.w;
    float ss = acc.x * acc.x + acc.y * acc.y + acc.z * acc.z + acc.w * acc.w;
#pragma unroll
    for (int off = 16; off > 0; off >>= 1) {
        s  += __shfl_xor_sync(0xffffffffu, s, off);
        ss += __shfl_xor_sync(0xffffffffu, ss, off);
    }
    float mu = s * (1.f / 128.f);
    float var = ss * (1.f / 128.f) - mu * mu;
    float rinv = rsqrtf(var + 1e-5f);

    float4 gg = ((const float4*)lng)[lane];
    float4 bb = ((const float4*)lnb)[lane];
    float4 xo = ((float4*)g_x)[(size_t)n * 32 + lane];
    float4 o;
    o.x = softplusf((acc.x - mu) * rinv * gg.x + bb.x + xo.x);
    o.y = softplusf((acc.y - mu) * rinv * gg.y + bb.y + xo.y);
    o.z = softplusf((acc.z - mu) * rinv * gg.z + bb.z + xo.z);
    o.w = softplusf((acc.w - mu) * rinv * gg.w + bb.w + xo.w);
    ((float4*)g_x)[(size_t)n * 32 + lane] = o;
}

// ---------------- mean pool (atomic) ----------------
__global__ void pool_kernel(const int* __restrict__ batch) {
    int n = blockIdx.x * 8 + (threadIdx.x >> 5);
    if (n >= N_NODES) return;
    int lane = threadIdx.x & 31;
    int b = 0;
    if (lane == 0) b = batch[n];
    b = __shfl_sync(0xffffffffu, b, 0);
    float4 v = ((const float4*)g_x)[(size_t)n * 32 + lane];
    float* base = g_pool + (size_t)b * NODE_D + 4 * lane;
    atomicAdd(base + 0, v.x);
    atomicAdd(base + 1, v.y);
    atomicAdd(base + 2, v.z);
    atomicAdd(base + 3, v.w);
    if (lane == 0) atomicAdd(g_cnt + b, 1.f);
}

// ---------------- head MLP: one block per graph ----------------
__global__ void head_kernel(const float* __restrict__ cfc_w, const float* __restrict__ cfc_b,
                            const float* __restrict__ fc_w,  const float* __restrict__ fc_b,
                            const float* __restrict__ out_w, const float* __restrict__ out_b,
                            float* __restrict__ out) {
    __shared__ float h0[FC_D], h1[FC_D];
    __shared__ float red[4];
    int g = blockIdx.x, c = threadIdx.x;
    float cn = fmaxf(g_cnt[g], 1.f);
    h0[c] = g_pool[(size_t)g * NODE_D + c] / cn;
    __syncthreads();
    float acc = cfc_b[c];
#pragma unroll 4
    for (int k = 0; k < NODE_D; k++) acc += h0[k] * cfc_w[k * FC_D + c];
    h1[c] = softplusf(acc);
    __syncthreads();
    acc = fc_b[c];
#pragma unroll 4
    for (int k = 0; k < FC_D; k++) acc += h1[k] * fc_w[k * FC_D + c];
    h0[c] = softplusf(acc);
    __syncthreads();
    acc = fc_b[FC_D + c];
#pragma unroll 4
    for (int k = 0; k < FC_D; k++) acc += h0[k] * fc_w[FC_D * FC_D + k * FC_D + c];
    h1[c] = softplusf(acc);
    __syncthreads();
    float p = h1[c] * out_w[c];
#pragma unroll
    for (int off = 16; off > 0; off >>= 1) p += __shfl_xor_sync(0xffffffffu, p, off);
    if ((c & 31) == 0) red[c >> 5] = p;
    __syncthreads();
    if (c == 0) out[g] = red[0] + red[1] + red[2] + red[3] + out_b[0];
}

// ---------------- launch ----------------
extern "C" void kernel_launch(void* const* d_in, const int* in_sizes, int n_in,
                              void* d_out, int out_size) {
    const int*   z         = (const int*)d_in[0];
    const float* R         = (const float*)d_in[1];
    const int*   ei        = (const int*)d_in[2];
    const int*   batch     = (const int*)d_in[3];
    const float* embedding = (const float*)d_in[4];
    const float* emb_w     = (const float*)d_in[5];
    const float* emb_b     = (const float*)d_in[6];
    const float* conv_w    = (const float*)d_in[7];
    const float* conv_b    = (const float*)d_in[8];
    const float* ln_g      = (const float*)d_in[9];
    const float* ln_b      = (const float*)d_in[10];
    const float* cfc_w     = (const float*)d_in[11];
    const float* cfc_b     = (const float*)d_in[12];
    const float* fc_w      = (const float*)d_in[13];
    const float* fc_b      = (const float*)d_in[14];
    const float* out_w     = (const float*)d_in[15];
    const float* out_b     = (const float*)d_in[16];
    float* out = (float*)d_out;

    const int* src = ei;
    const int* dst = ei + N_EDGES;

    // zero counters + pool
    zero_misc_kernel<<<(N_GRAPHS * NODE_D + 255) / 256 + 200, 256>>>();
    // initial node features
    embed_kernel<<<N_NODES, NODE_D>>>(z, embedding, emb_w, emb_b);
    // counting sort of edges by dst (+ per-edge distance -> table coords)
    hist_kernel<<<(N_EDGES + 255) / 256, 256>>>(dst);
    scan_kernel<<<1, 1024>>>();
    scatter_kernel<<<(N_EDGES + 255) / 256, 256>>>(R, src, dst);

    for (int l = 0; l < N_CONV; l++) {
        const float* Wl = conv_w + (size_t)l * 356 * 256;
        const float* bl = conv_b + (size_t)l * 256;
        build_tab_kernel<<<N_T, 256>>>(Wl);
        dim3 ggrid(512 / GN, (N_NODES + GM - 1) / GM);
        gemm_ab_kernel<<<ggrid, 256>>>(Wl, bl);
        edge_agg_kernel<<<(N_NODES + 7) / 8, 256>>>(ln_g + l * NODE_D, ln_b + l * NODE_D);
    }

    pool_kernel<<<(N_NODES + 7) / 8, 256>>>(batch);
    head_kernel<<<N_GRAPHS, FC_D>>>(cfc_w, cfc_b, fc_w, fc_b, out_w, out_b, out);
}